// round 9
// baseline (speedup 1.0000x reference)
#include <cuda_runtime.h>
#include <cuda_bf16.h>
#include <math.h>
#include <stdint.h>

#define NN 50000
#define NE 800000
#define NHEADS 8
#define HID 256
#define NCLS 40
#define NEG 0.2f

// ---------------- scratch (static device allocations; no cudaMalloc) ----------------
__device__ __nv_bfloat16 g_featb[(size_t)NN * HID];
__device__ float g_hbuf[(size_t)NN * HID];
__device__ float g_feat2[(size_t)NN * NCLS];
__device__ float g_el[NN * NHEADS];
__device__ float g_er[NN * NHEADS];
__device__ float g_el2[NN];
__device__ float g_er2[NN];
__device__ int   g_deg[NN];
__device__ int   g_cur[NN];
__device__ int   g_off[NN + 1];
__device__ int   g_csr_src[NE];
__device__ __nv_bfloat16 g_w0hi[512 * HID];
__device__ __nv_bfloat16 g_w0lo[512 * HID];
__device__ __nv_bfloat16 g_w1hi[HID * HID];
__device__ __nv_bfloat16 g_w1lo[HID * HID];
__device__ __nv_bfloat16 g_w2hi[64 * HID];   // rows 40..63 stay zero
__device__ __nv_bfloat16 g_w2lo[64 * HID];

// ---------------- CSR build ----------------
__global__ void zero_counts_kernel() {
    int i = blockIdx.x * blockDim.x + threadIdx.x;
    if (i < NN) { g_deg[i] = 0; g_cur[i] = 0; }
}
__global__ void hist_kernel(const int* __restrict__ dst) {
    int e = blockIdx.x * blockDim.x + threadIdx.x;
    if (e < NE) atomicAdd(&g_deg[dst[e]], 1);
}
__global__ void scan_kernel() {
    __shared__ int sums[1024];
    int t = threadIdx.x;
    const int chunk = (NN + 1023) / 1024;
    int start = t * chunk;
    int end = min(start + chunk, NN);
    int s = 0;
    for (int i = start; i < end; i++) s += g_deg[i];
    sums[t] = s;
    __syncthreads();
    for (int off = 1; off < 1024; off <<= 1) {
        int v = (t >= off) ? sums[t - off] : 0;
        __syncthreads();
        sums[t] += v;
        __syncthreads();
    }
    int run = (t == 0) ? 0 : sums[t - 1];
    for (int i = start; i < end; i++) { g_off[i] = run; run += g_deg[i]; }
    if (t == 1023) g_off[NN] = sums[1023];
}
__global__ void scatter_kernel(const int* __restrict__ src, const int* __restrict__ dst) {
    int e = blockIdx.x * blockDim.x + threadIdx.x;
    if (e < NE) {
        int d = dst[e];
        int pos = g_off[d] + atomicAdd(&g_cur[d], 1);
        g_csr_src[pos] = src[e];
    }
}

// ---------------- weight prep: W[K,Ncols] fp32 -> Wt[Ncols,K] bf16 hi/lo ----------------
__global__ void prep_wt(const float* __restrict__ W, __nv_bfloat16* __restrict__ hi,
                        __nv_bfloat16* __restrict__ lo, int K, int Ncols) {
    int idx = blockIdx.x * blockDim.x + threadIdx.x;
    if (idx >= K * Ncols) return;
    int k = idx / Ncols;
    int n = idx - k * Ncols;
    float x = W[idx];
    __nv_bfloat16 h = __float2bfloat16(x);
    float r = x - __bfloat162float(h);
    hi[(size_t)n * K + k] = h;
    lo[(size_t)n * K + k] = __float2bfloat16(r);
}

// ---------------- warp-mma bf16-split GEMM (3-term), pipelined, fused el/er ----------------
#define SPITCH 20

#define MMA_BF16(c, a, b)                                                           \
    asm volatile(                                                                   \
        "mma.sync.aligned.m16n8k16.row.col.f32.bf16.bf16.f32 "                      \
        "{%0,%1,%2,%3},{%4,%5,%6,%7},{%8,%9},{%0,%1,%2,%3};"                        \
        : "+f"((c)[0]), "+f"((c)[1]), "+f"((c)[2]), "+f"((c)[3])                    \
        : "r"((a)[0]), "r"((a)[1]), "r"((a)[2]), "r"((a)[3]),                       \
          "r"((b)[0]), "r"((b)[1]))

__global__ __launch_bounds__(256, 1) void gemm_mma(
    const float* __restrict__ A, const __nv_bfloat16* __restrict__ Bhi,
    const __nv_bfloat16* __restrict__ Blo, const float* __restrict__ alv,
    const float* __restrict__ arv, __nv_bfloat16* __restrict__ featb,
    float* __restrict__ el, float* __restrict__ er, int K)
{
    __shared__ uint32_t sAh[128 * SPITCH];
    __shared__ uint32_t sAl[128 * SPITCH];
    __shared__ uint32_t sBh[128 * SPITCH];
    __shared__ uint32_t sBl[128 * SPITCH];

    int tid = threadIdx.x, lane = tid & 31, wid = tid >> 5;
    int wm = wid & 1, wn = wid >> 1;
    int row0 = blockIdx.x * 128;
    int col0 = blockIdx.y * 128;
    const uint2* Bh64 = (const uint2*)Bhi;
    const uint2* Bl64 = (const uint2*)Blo;
    int Kq = K >> 2;

    int lr = tid >> 3;
    int lq = tid & 7;

    float acc[4][4][4];
#pragma unroll
    for (int i = 0; i < 4; i++)
#pragma unroll
        for (int j = 0; j < 4; j++)
#pragma unroll
            for (int q = 0; q < 4; q++) acc[i][j][q] = 0.f;

    float4 pa[4];
    uint2 pbh[4], pbl[4];
    int nch = K >> 5;

#pragma unroll
    for (int i = 0; i < 4; i++) {
        int r = lr + i * 32;
        pa[i] = (row0 + r < NN)
            ? *(const float4*)(A + (size_t)(row0 + r) * K + lq * 4)
            : make_float4(0.f, 0.f, 0.f, 0.f);
        pbh[i] = Bh64[(size_t)(col0 + r) * Kq + lq];
        pbl[i] = Bl64[(size_t)(col0 + r) * Kq + lq];
    }

    for (int c = 0; c < nch; c++) {
#pragma unroll
        for (int i = 0; i < 4; i++) {
            int r = lr + i * 32;
            float4 v = pa[i];
            __nv_bfloat16 h0 = __float2bfloat16(v.x);
            __nv_bfloat16 h1 = __float2bfloat16(v.y);
            __nv_bfloat16 h2 = __float2bfloat16(v.z);
            __nv_bfloat16 h3 = __float2bfloat16(v.w);
            __nv_bfloat16 l0 = __float2bfloat16(v.x - __bfloat162float(h0));
            __nv_bfloat16 l1 = __float2bfloat16(v.y - __bfloat162float(h1));
            __nv_bfloat16 l2 = __float2bfloat16(v.z - __bfloat162float(h2));
            __nv_bfloat16 l3 = __float2bfloat16(v.w - __bfloat162float(h3));
            int sb = r * SPITCH + lq * 2;
            sAh[sb]     = (uint32_t)__bfloat16_as_ushort(h0) | ((uint32_t)__bfloat16_as_ushort(h1) << 16);
            sAh[sb + 1] = (uint32_t)__bfloat16_as_ushort(h2) | ((uint32_t)__bfloat16_as_ushort(h3) << 16);
            sAl[sb]     = (uint32_t)__bfloat16_as_ushort(l0) | ((uint32_t)__bfloat16_as_ushort(l1) << 16);
            sAl[sb + 1] = (uint32_t)__bfloat16_as_ushort(l2) | ((uint32_t)__bfloat16_as_ushort(l3) << 16);
            sBh[sb]     = pbh[i].x;
            sBh[sb + 1] = pbh[i].y;
            sBl[sb]     = pbl[i].x;
            sBl[sb + 1] = pbl[i].y;
        }
        __syncthreads();

        if (c + 1 < nch) {
            int ko = (c + 1) << 5;
#pragma unroll
            for (int i = 0; i < 4; i++) {
                int r = lr + i * 32;
                pa[i] = (row0 + r < NN)
                    ? *(const float4*)(A + (size_t)(row0 + r) * K + ko + lq * 4)
                    : make_float4(0.f, 0.f, 0.f, 0.f);
                pbh[i] = Bh64[(size_t)(col0 + r) * Kq + ((c + 1) << 3) + lq];
                pbl[i] = Bl64[(size_t)(col0 + r) * Kq + ((c + 1) << 3) + lq];
            }
        }

#pragma unroll
        for (int ks = 0; ks < 2; ks++) {
            int kb = (ks << 3) + (lane & 3);
            uint32_t ah[4][4], al_[4][4], bh[4][2], bl[4][2];
#pragma unroll
            for (int am = 0; am < 4; am++) {
                int rb = (wm * 64 + am * 16 + (lane >> 2)) * SPITCH;
                ah[am][0] = sAh[rb + kb];
                ah[am][1] = sAh[rb + 8 * SPITCH + kb];
                ah[am][2] = sAh[rb + kb + 4];
                ah[am][3] = sAh[rb + 8 * SPITCH + kb + 4];
                al_[am][0] = sAl[rb + kb];
                al_[am][1] = sAl[rb + 8 * SPITCH + kb];
                al_[am][2] = sAl[rb + kb + 4];
                al_[am][3] = sAl[rb + 8 * SPITCH + kb + 4];
            }
#pragma unroll
            for (int an = 0; an < 4; an++) {
                int nb = (wn * 32 + an * 8 + (lane >> 2)) * SPITCH;
                bh[an][0] = sBh[nb + kb];
                bh[an][1] = sBh[nb + kb + 4];
                bl[an][0] = sBl[nb + kb];
                bl[an][1] = sBl[nb + kb + 4];
            }
#pragma unroll
            for (int am = 0; am < 4; am++)
#pragma unroll
                for (int an = 0; an < 4; an++) {
                    MMA_BF16(acc[am][an], ah[am], bh[an]);
                    MMA_BF16(acc[am][an], ah[am], bl[an]);
                    MMA_BF16(acc[am][an], al_[am], bh[an]);
                }
        }
        __syncthreads();
    }

    int h = blockIdx.y * 4 + wn;
    float alr[8], arr[8];
#pragma unroll
    for (int an = 0; an < 4; an++) {
        int cc = an * 8 + 2 * (lane & 3);
        alr[an * 2]     = __ldg(alv + h * 32 + cc);
        alr[an * 2 + 1] = __ldg(alv + h * 32 + cc + 1);
        arr[an * 2]     = __ldg(arv + h * 32 + cc);
        arr[an * 2 + 1] = __ldg(arv + h * 32 + cc + 1);
    }
#pragma unroll
    for (int am = 0; am < 4; am++) {
        int r0 = row0 + wm * 64 + am * 16 + (lane >> 2);
        int r1 = r0 + 8;
        float sl0 = 0.f, sr0 = 0.f, sl1 = 0.f, sr1 = 0.f;
#pragma unroll
        for (int an = 0; an < 4; an++) {
            float c0 = acc[am][an][0], c1 = acc[am][an][1];
            float c2 = acc[am][an][2], c3 = acc[am][an][3];
            sl0 = fmaf(c0, alr[an * 2], fmaf(c1, alr[an * 2 + 1], sl0));
            sr0 = fmaf(c0, arr[an * 2], fmaf(c1, arr[an * 2 + 1], sr0));
            sl1 = fmaf(c2, alr[an * 2], fmaf(c3, alr[an * 2 + 1], sl1));
            sr1 = fmaf(c2, arr[an * 2], fmaf(c3, arr[an * 2 + 1], sr1));
            int ccol = col0 + wn * 32 + an * 8 + 2 * (lane & 3);
            __nv_bfloat162 p0 = __float22bfloat162_rn(make_float2(c0, c1));
            __nv_bfloat162 p1 = __float22bfloat162_rn(make_float2(c2, c3));
            if (r0 < NN) *(__nv_bfloat162*)(featb + (size_t)r0 * HID + ccol) = p0;
            if (r1 < NN) *(__nv_bfloat162*)(featb + (size_t)r1 * HID + ccol) = p1;
        }
        sl0 += __shfl_xor_sync(0xFFFFFFFFu, sl0, 1);
        sl0 += __shfl_xor_sync(0xFFFFFFFFu, sl0, 2);
        sr0 += __shfl_xor_sync(0xFFFFFFFFu, sr0, 1);
        sr0 += __shfl_xor_sync(0xFFFFFFFFu, sr0, 2);
        sl1 += __shfl_xor_sync(0xFFFFFFFFu, sl1, 1);
        sl1 += __shfl_xor_sync(0xFFFFFFFFu, sl1, 2);
        sr1 += __shfl_xor_sync(0xFFFFFFFFu, sr1, 1);
        sr1 += __shfl_xor_sync(0xFFFFFFFFu, sr1, 2);
        if ((lane & 3) == 0) {
            if (r0 < NN) { el[r0 * NHEADS + h] = sl0; er[r0 * NHEADS + h] = sr0; }
            if (r1 < NN) { el[r1 * NHEADS + h] = sl1; er[r1 * NHEADS + h] = sr1; }
        }
    }
}

// ---------------- classifier GEMM + fused el2/er2: feat2[M,40] = A[M,256] @ W2 ----------------
__global__ __launch_bounds__(256, 1) void gemm_mma2(
    const float* __restrict__ A, const __nv_bfloat16* __restrict__ Bhi,
    const __nv_bfloat16* __restrict__ Blo, const float* __restrict__ al2,
    const float* __restrict__ ar2, float* __restrict__ feat2,
    float* __restrict__ el2, float* __restrict__ er2)
{
    __shared__ uint32_t sAh[128 * SPITCH];
    __shared__ uint32_t sAl[128 * SPITCH];
    __shared__ uint32_t sBh[64 * SPITCH];
    __shared__ uint32_t sBl[64 * SPITCH];
    __shared__ float sEl[128], sEr[128];

    const int K = HID;
    int tid = threadIdx.x, lane = tid & 31, wid = tid >> 5;
    int wm = wid & 1, wn = wid >> 1;
    int row0 = blockIdx.x * 128;
    const uint2* Bh64 = (const uint2*)Bhi;
    const uint2* Bl64 = (const uint2*)Blo;
    const int Kq = K >> 2;

    int lr = tid >> 3;
    int lq = tid & 7;

    float acc[4][2][4];
#pragma unroll
    for (int i = 0; i < 4; i++)
#pragma unroll
        for (int j = 0; j < 2; j++)
#pragma unroll
            for (int q = 0; q < 4; q++) acc[i][j][q] = 0.f;

    float4 pa[4];
    uint2 pbh[2], pbl[2];
    const int nch = K >> 5;

#pragma unroll
    for (int i = 0; i < 4; i++) {
        int r = lr + i * 32;
        pa[i] = (row0 + r < NN)
            ? *(const float4*)(A + (size_t)(row0 + r) * K + lq * 4)
            : make_float4(0.f, 0.f, 0.f, 0.f);
    }
#pragma unroll
    for (int i = 0; i < 2; i++) {
        int r = lr + i * 32;
        pbh[i] = Bh64[(size_t)r * Kq + lq];
        pbl[i] = Bl64[(size_t)r * Kq + lq];
    }

    for (int c = 0; c < nch; c++) {
#pragma unroll
        for (int i = 0; i < 4; i++) {
            int r = lr + i * 32;
            float4 v = pa[i];
            __nv_bfloat16 h0 = __float2bfloat16(v.x);
            __nv_bfloat16 h1 = __float2bfloat16(v.y);
            __nv_bfloat16 h2 = __float2bfloat16(v.z);
            __nv_bfloat16 h3 = __float2bfloat16(v.w);
            __nv_bfloat16 l0 = __float2bfloat16(v.x - __bfloat162float(h0));
            __nv_bfloat16 l1 = __float2bfloat16(v.y - __bfloat162float(h1));
            __nv_bfloat16 l2 = __float2bfloat16(v.z - __bfloat162float(h2));
            __nv_bfloat16 l3 = __float2bfloat16(v.w - __bfloat162float(h3));
            int sb = r * SPITCH + lq * 2;
            sAh[sb]     = (uint32_t)__bfloat16_as_ushort(h0) | ((uint32_t)__bfloat16_as_ushort(h1) << 16);
            sAh[sb + 1] = (uint32_t)__bfloat16_as_ushort(h2) | ((uint32_t)__bfloat16_as_ushort(h3) << 16);
            sAl[sb]     = (uint32_t)__bfloat16_as_ushort(l0) | ((uint32_t)__bfloat16_as_ushort(l1) << 16);
            sAl[sb + 1] = (uint32_t)__bfloat16_as_ushort(l2) | ((uint32_t)__bfloat16_as_ushort(l3) << 16);
        }
#pragma unroll
        for (int i = 0; i < 2; i++) {
            int r = lr + i * 32;
            int sb = r * SPITCH + lq * 2;
            sBh[sb]     = pbh[i].x;
            sBh[sb + 1] = pbh[i].y;
            sBl[sb]     = pbl[i].x;
            sBl[sb + 1] = pbl[i].y;
        }
        __syncthreads();

        if (c + 1 < nch) {
            int ko = (c + 1) << 5;
#pragma unroll
            for (int i = 0; i < 4; i++) {
                int r = lr + i * 32;
                pa[i] = (row0 + r < NN)
                    ? *(const float4*)(A + (size_t)(row0 + r) * K + ko + lq * 4)
                    : make_float4(0.f, 0.f, 0.f, 0.f);
            }
#pragma unroll
            for (int i = 0; i < 2; i++) {
                int r = lr + i * 32;
                pbh[i] = Bh64[(size_t)r * Kq + ((c + 1) << 3) + lq];
                pbl[i] = Bl64[(size_t)r * Kq + ((c + 1) << 3) + lq];
            }
        }

#pragma unroll
        for (int ks = 0; ks < 2; ks++) {
            int kb = (ks << 3) + (lane & 3);
            uint32_t ah[4][4], al_[4][4], bh[2][2], bl[2][2];
#pragma unroll
            for (int am = 0; am < 4; am++) {
                int rb = (wm * 64 + am * 16 + (lane >> 2)) * SPITCH;
                ah[am][0] = sAh[rb + kb];
                ah[am][1] = sAh[rb + 8 * SPITCH + kb];
                ah[am][2] = sAh[rb + kb + 4];
                ah[am][3] = sAh[rb + 8 * SPITCH + kb + 4];
                al_[am][0] = sAl[rb + kb];
                al_[am][1] = sAl[rb + 8 * SPITCH + kb];
                al_[am][2] = sAl[rb + kb + 4];
                al_[am][3] = sAl[rb + 8 * SPITCH + kb + 4];
            }
#pragma unroll
            for (int an = 0; an < 2; an++) {
                int nb = (wn * 16 + an * 8 + (lane >> 2)) * SPITCH;
                bh[an][0] = sBh[nb + kb];
                bh[an][1] = sBh[nb + kb + 4];
                bl[an][0] = sBl[nb + kb];
                bl[an][1] = sBl[nb + kb + 4];
            }
#pragma unroll
            for (int am = 0; am < 4; am++)
#pragma unroll
                for (int an = 0; an < 2; an++) {
                    MMA_BF16(acc[am][an], ah[am], bh[an]);
                    MMA_BF16(acc[am][an], ah[am], bl[an]);
                    MMA_BF16(acc[am][an], al_[am], bh[an]);
                }
        }
        __syncthreads();
    }

    // fused el2/er2: zero smem accumulators
    if (tid < 128) { sEl[tid] = 0.f; sEr[tid] = 0.f; }
    __syncthreads();

    // attention vectors for this warp's columns (zero outside NCLS)
    float av[4], rv[4];
#pragma unroll
    for (int an = 0; an < 2; an++) {
        int cc = wn * 16 + an * 8 + 2 * (lane & 3);
        av[an * 2]     = (cc < NCLS)     ? __ldg(al2 + cc)     : 0.f;
        av[an * 2 + 1] = (cc + 1 < NCLS) ? __ldg(al2 + cc + 1) : 0.f;
        rv[an * 2]     = (cc < NCLS)     ? __ldg(ar2 + cc)     : 0.f;
        rv[an * 2 + 1] = (cc + 1 < NCLS) ? __ldg(ar2 + cc + 1) : 0.f;
    }

#pragma unroll
    for (int am = 0; am < 4; am++) {
        int rl0 = wm * 64 + am * 16 + (lane >> 2);
        int rl1 = rl0 + 8;
        int r0 = row0 + rl0, r1 = row0 + rl1;
        float sl0 = 0.f, sr0 = 0.f, sl1 = 0.f, sr1 = 0.f;
#pragma unroll
        for (int an = 0; an < 2; an++) {
            float c0 = acc[am][an][0], c1 = acc[am][an][1];
            float c2 = acc[am][an][2], c3 = acc[am][an][3];
            sl0 = fmaf(c0, av[an * 2], fmaf(c1, av[an * 2 + 1], sl0));
            sr0 = fmaf(c0, rv[an * 2], fmaf(c1, rv[an * 2 + 1], sr0));
            sl1 = fmaf(c2, av[an * 2], fmaf(c3, av[an * 2 + 1], sl1));
            sr1 = fmaf(c2, rv[an * 2], fmaf(c3, rv[an * 2 + 1], sr1));
            int ccol = wn * 16 + an * 8 + 2 * (lane & 3);
            if (ccol < NCLS) {
                if (r0 < NN)
                    *(float2*)(feat2 + (size_t)r0 * NCLS + ccol) = make_float2(c0, c1);
                if (r1 < NN)
                    *(float2*)(feat2 + (size_t)r1 * NCLS + ccol) = make_float2(c2, c3);
            }
        }
        sl0 += __shfl_xor_sync(0xFFFFFFFFu, sl0, 1);
        sl0 += __shfl_xor_sync(0xFFFFFFFFu, sl0, 2);
        sr0 += __shfl_xor_sync(0xFFFFFFFFu, sr0, 1);
        sr0 += __shfl_xor_sync(0xFFFFFFFFu, sr0, 2);
        sl1 += __shfl_xor_sync(0xFFFFFFFFu, sl1, 1);
        sl1 += __shfl_xor_sync(0xFFFFFFFFu, sl1, 2);
        sr1 += __shfl_xor_sync(0xFFFFFFFFu, sr1, 1);
        sr1 += __shfl_xor_sync(0xFFFFFFFFu, sr1, 2);
        if ((lane & 3) == 0) {
            atomicAdd(&sEl[rl0], sl0);
            atomicAdd(&sEr[rl0], sr0);
            atomicAdd(&sEl[rl1], sl1);
            atomicAdd(&sEr[rl1], sr1);
        }
    }
    __syncthreads();
    if (tid < 128) {
        int r = row0 + tid;
        if (r < NN) { el2[r] = sEl[tid]; er2[r] = sEr[tid]; }
    }
}

// ---------------- per-dst dual-stream online-softmax aggregation (bf16 msgs) ----------------
__global__ __launch_bounds__(256) void agg_kernel(const __nv_bfloat16* __restrict__ featb,
                                                  const float* __restrict__ el,
                                                  const float* __restrict__ er,
                                                  const float* __restrict__ bias,
                                                  float* __restrict__ out) {
    int gw = (blockIdx.x * blockDim.x + threadIdx.x) >> 5;
    int lane = threadIdx.x & 31;
    if (gw >= NN) return;
    int h = lane >> 2;
    float erh = er[gw * NHEADS + h];
    int e0 = g_off[gw], e1 = g_off[gw + 1];
    float m0 = -1e30f, d0 = 0.f, m1 = -1e30f, d1 = 0.f;
    float a0[8], a1[8];
#pragma unroll
    for (int j = 0; j < 8; j++) { a0[j] = 0.f; a1[j] = 0.f; }

    int i = e0;
    for (; i + 1 < e1; i += 2) {
        int s0 = g_csr_src[i];
        int s1 = g_csr_src[i + 1];
        float sc0 = el[s0 * NHEADS + h] + erh;
        float sc1 = el[s1 * NHEADS + h] + erh;
        sc0 = (sc0 > 0.f) ? sc0 : NEG * sc0;
        sc1 = (sc1 > 0.f) ? sc1 : NEG * sc1;
        uint4 q0 = *(const uint4*)(featb + (size_t)s0 * HID + lane * 8);
        uint4 q1 = *(const uint4*)(featb + (size_t)s1 * HID + lane * 8);

        float mn0 = fmaxf(m0, sc0);
        float sk0 = __expf(m0 - mn0);
        float p0 = __expf(sc0 - mn0);
        m0 = mn0;
        d0 = d0 * sk0 + p0;
        float2 v;
        v = __bfloat1622float2(*(__nv_bfloat162*)&q0.x);
        a0[0] = fmaf(p0, v.x, a0[0] * sk0); a0[1] = fmaf(p0, v.y, a0[1] * sk0);
        v = __bfloat1622float2(*(__nv_bfloat162*)&q0.y);
        a0[2] = fmaf(p0, v.x, a0[2] * sk0); a0[3] = fmaf(p0, v.y, a0[3] * sk0);
        v = __bfloat1622float2(*(__nv_bfloat162*)&q0.z);
        a0[4] = fmaf(p0, v.x, a0[4] * sk0); a0[5] = fmaf(p0, v.y, a0[5] * sk0);
        v = __bfloat1622float2(*(__nv_bfloat162*)&q0.w);
        a0[6] = fmaf(p0, v.x, a0[6] * sk0); a0[7] = fmaf(p0, v.y, a0[7] * sk0);

        float mn1 = fmaxf(m1, sc1);
        float sk1 = __expf(m1 - mn1);
        float p1 = __expf(sc1 - mn1);
        m1 = mn1;
        d1 = d1 * sk1 + p1;
        v = __bfloat1622float2(*(__nv_bfloat162*)&q1.x);
        a1[0] = fmaf(p1, v.x, a1[0] * sk1); a1[1] = fmaf(p1, v.y, a1[1] * sk1);
        v = __bfloat1622float2(*(__nv_bfloat162*)&q1.y);
        a1[2] = fmaf(p1, v.x, a1[2] * sk1); a1[3] = fmaf(p1, v.y, a1[3] * sk1);
        v = __bfloat1622float2(*(__nv_bfloat162*)&q1.z);
        a1[4] = fmaf(p1, v.x, a1[4] * sk1); a1[5] = fmaf(p1, v.y, a1[5] * sk1);
        v = __bfloat1622float2(*(__nv_bfloat162*)&q1.w);
        a1[6] = fmaf(p1, v.x, a1[6] * sk1); a1[7] = fmaf(p1, v.y, a1[7] * sk1);
    }
    if (i < e1) {
        int s0 = g_csr_src[i];
        float sc0 = el[s0 * NHEADS + h] + erh;
        sc0 = (sc0 > 0.f) ? sc0 : NEG * sc0;
        uint4 q0 = *(const uint4*)(featb + (size_t)s0 * HID + lane * 8);
        float mn0 = fmaxf(m0, sc0);
        float sk0 = __expf(m0 - mn0);
        float p0 = __expf(sc0 - mn0);
        m0 = mn0;
        d0 = d0 * sk0 + p0;
        float2 v;
        v = __bfloat1622float2(*(__nv_bfloat162*)&q0.x);
        a0[0] = fmaf(p0, v.x, a0[0] * sk0); a0[1] = fmaf(p0, v.y, a0[1] * sk0);
        v = __bfloat1622float2(*(__nv_bfloat162*)&q0.y);
        a0[2] = fmaf(p0, v.x, a0[2] * sk0); a0[3] = fmaf(p0, v.y, a0[3] * sk0);
        v = __bfloat1622float2(*(__nv_bfloat162*)&q0.z);
        a0[4] = fmaf(p0, v.x, a0[4] * sk0); a0[5] = fmaf(p0, v.y, a0[5] * sk0);
        v = __bfloat1622float2(*(__nv_bfloat162*)&q0.w);
        a0[6] = fmaf(p0, v.x, a0[6] * sk0); a0[7] = fmaf(p0, v.y, a0[7] * sk0);
    }

    // merge streams
    float mn = fmaxf(m0, m1);
    float s0m = __expf(m0 - mn), s1m = __expf(m1 - mn);
    float den = d0 * s0m + d1 * s1m;
    float rinv = 1.f / fmaxf(den, 1e-9f);
    float4 b0v = *(const float4*)(bias + lane * 8);
    float4 b1v = *(const float4*)(bias + lane * 8 + 4);
    float oc[8];
#pragma unroll
    for (int j = 0; j < 8; j++) oc[j] = a0[j] * s0m + a1[j] * s1m;
    float4 o0, o1;
    o0.x = fmaxf(fmaf(oc[0], rinv, b0v.x), 0.f);
    o0.y = fmaxf(fmaf(oc[1], rinv, b0v.y), 0.f);
    o0.z = fmaxf(fmaf(oc[2], rinv, b0v.z), 0.f);
    o0.w = fmaxf(fmaf(oc[3], rinv, b0v.w), 0.f);
    o1.x = fmaxf(fmaf(oc[4], rinv, b1v.x), 0.f);
    o1.y = fmaxf(fmaf(oc[5], rinv, b1v.y), 0.f);
    o1.z = fmaxf(fmaf(oc[6], rinv, b1v.z), 0.f);
    o1.w = fmaxf(fmaf(oc[7], rinv, b1v.w), 0.f);
    float4* op = (float4*)(out + (size_t)gw * HID + lane * 8);
    op[0] = o0;
    op[1] = o1;
}

// ---------------- classifier aggregation (H=1, D=40), dual-stream, no relu ----------------
__global__ __launch_bounds__(256) void agg2_kernel(const float* __restrict__ feat,
                                                   const float* __restrict__ el,
                                                   const float* __restrict__ er,
                                                   const float* __restrict__ bias,
                                                   float* __restrict__ out) {
    int gw = (blockIdx.x * blockDim.x + threadIdx.x) >> 5;
    int lane = threadIdx.x & 31;
    if (gw >= NN) return;
    float ern = er[gw];
    int e0 = g_off[gw], e1 = g_off[gw + 1];
    float m0 = -1e30f, d0 = 0.f, x00 = 0.f, x01 = 0.f;
    float m1 = -1e30f, d1 = 0.f, x10 = 0.f, x11 = 0.f;

    int i = e0;
    for (; i + 1 < e1; i += 2) {
        int s0 = g_csr_src[i];
        int s1 = g_csr_src[i + 1];
        float sc0 = el[s0] + ern;
        float sc1 = el[s1] + ern;
        sc0 = (sc0 > 0.f) ? sc0 : NEG * sc0;
        sc1 = (sc1 > 0.f) ? sc1 : NEG * sc1;
        float f00 = feat[(size_t)s0 * NCLS + lane];
        float f01 = (lane < 8) ? feat[(size_t)s0 * NCLS + 32 + lane] : 0.f;
        float f10 = feat[(size_t)s1 * NCLS + lane];
        float f11 = (lane < 8) ? feat[(size_t)s1 * NCLS + 32 + lane] : 0.f;

        float mn0 = fmaxf(m0, sc0);
        float sk0 = __expf(m0 - mn0);
        float p0 = __expf(sc0 - mn0);
        m0 = mn0;
        d0 = d0 * sk0 + p0;
        x00 = fmaf(p0, f00, x00 * sk0);
        x01 = fmaf(p0, f01, x01 * sk0);

        float mn1 = fmaxf(m1, sc1);
        float sk1 = __expf(m1 - mn1);
        float p1 = __expf(sc1 - mn1);
        m1 = mn1;
        d1 = d1 * sk1 + p1;
        x10 = fmaf(p1, f10, x10 * sk1);
        x11 = fmaf(p1, f11, x11 * sk1);
    }
    if (i < e1) {
        int s0 = g_csr_src[i];
        float sc0 = el[s0] + ern;
        sc0 = (sc0 > 0.f) ? sc0 : NEG * sc0;
        float f00 = feat[(size_t)s0 * NCLS + lane];
        float f01 = (lane < 8) ? feat[(size_t)s0 * NCLS + 32 + lane] : 0.f;
        float mn0 = fmaxf(m0, sc0);
        float sk0 = __expf(m0 - mn0);
        float p0 = __expf(sc0 - mn0);
        m0 = mn0;
        d0 = d0 * sk0 + p0;
        x00 = fmaf(p0, f00, x00 * sk0);
        x01 = fmaf(p0, f01, x01 * sk0);
    }

    float mn = fmaxf(m0, m1);
    float s0m = __expf(m0 - mn), s1m = __expf(m1 - mn);
    float den = d0 * s0m + d1 * s1m;
    float rinv = 1.f / fmaxf(den, 1e-9f);
    float v0 = x00 * s0m + x10 * s1m;
    float v1 = x01 * s0m + x11 * s1m;
    out[(size_t)gw * NCLS + lane] = fmaf(v0, rinv, bias[lane]);
    if (lane < 8)
        out[(size_t)gw * NCLS + 32 + lane] = fmaf(v1, rinv, bias[32 + lane]);
}

// ---------------- launch ----------------
extern "C" void kernel_launch(void* const* d_in, const int* in_sizes, int n_in,
                              void* d_out, int out_size) {
    const float* in_feat = (const float*)d_in[0];
    const int*   src     = (const int*)d_in[1];
    const int*   dst     = (const int*)d_in[2];
    const float* W0  = (const float*)d_in[3];
    const float* al0 = (const float*)d_in[4];
    const float* ar0 = (const float*)d_in[5];
    const float* b0  = (const float*)d_in[6];
    const float* W1  = (const float*)d_in[7];
    const float* al1 = (const float*)d_in[8];
    const float* ar1 = (const float*)d_in[9];
    const float* b1  = (const float*)d_in[10];
    const float* W2  = (const float*)d_in[11];
    const float* al2 = (const float*)d_in[12];
    const float* ar2 = (const float*)d_in[13];
    const float* b2  = (const float*)d_in[14];
    float* out = (float*)d_out;

    float *p_h, *p_feat2, *p_el, *p_er, *p_el2, *p_er2;
    __nv_bfloat16 *p_featb, *p_w0hi, *p_w0lo, *p_w1hi, *p_w1lo, *p_w2hi, *p_w2lo;
    cudaGetSymbolAddress((void**)&p_featb, g_featb);
    cudaGetSymbolAddress((void**)&p_h, g_hbuf);
    cudaGetSymbolAddress((void**)&p_feat2, g_feat2);
    cudaGetSymbolAddress((void**)&p_el, g_el);
    cudaGetSymbolAddress((void**)&p_er, g_er);
    cudaGetSymbolAddress((void**)&p_el2, g_el2);
    cudaGetSymbolAddress((void**)&p_er2, g_er2);
    cudaGetSymbolAddress((void**)&p_w0hi, g_w0hi);
    cudaGetSymbolAddress((void**)&p_w0lo, g_w0lo);
    cudaGetSymbolAddress((void**)&p_w1hi, g_w1hi);
    cudaGetSymbolAddress((void**)&p_w1lo, g_w1lo);
    cudaGetSymbolAddress((void**)&p_w2hi, g_w2hi);
    cudaGetSymbolAddress((void**)&p_w2lo, g_w2lo);

    // lazily-created side stream + events (created once, outside any capture)
    static cudaStream_t s_side = nullptr;
    static cudaEvent_t s_fork = nullptr, s_join = nullptr;
    if (s_side == nullptr) {
        cudaStreamCreateWithFlags(&s_side, cudaStreamNonBlocking);
        cudaEventCreateWithFlags(&s_fork, cudaEventDisableTiming);
        cudaEventCreateWithFlags(&s_join, cudaEventDisableTiming);
    }

    // ---- fork: CSR build + W1/W2 prep on side stream ----
    cudaEventRecord(s_fork, 0);
    cudaStreamWaitEvent(s_side, s_fork, 0);
    zero_counts_kernel<<<(NN + 255) / 256, 256, 0, s_side>>>();
    hist_kernel<<<(NE + 255) / 256, 256, 0, s_side>>>(dst);
    scan_kernel<<<1, 1024, 0, s_side>>>();
    scatter_kernel<<<(NE + 255) / 256, 256, 0, s_side>>>(src, dst);
    prep_wt<<<(HID * HID + 255) / 256, 256, 0, s_side>>>(W1, p_w1hi, p_w1lo, HID, HID);
    prep_wt<<<(HID * NCLS + 255) / 256, 256, 0, s_side>>>(W2, p_w2hi, p_w2lo, HID, NCLS);
    cudaEventRecord(s_join, s_side);

    // ---- main stream: W0 prep + GEMM layer 0 ----
    prep_wt<<<(512 * HID + 255) / 256, 256>>>(W0, p_w0hi, p_w0lo, 512, HID);

    dim3 gemm_grid((NN + 127) / 128, 2);
    int agg_grid = (NN * 32 + 255) / 256;

    gemm_mma<<<gemm_grid, 256>>>(in_feat, p_w0hi, p_w0lo, al0, ar0,
                                 p_featb, p_el, p_er, 512);

    // join side stream before aggregation
    cudaStreamWaitEvent(0, s_join, 0);
    agg_kernel<<<agg_grid, 256>>>(p_featb, p_el, p_er, b0, p_h);

    // layer 1
    gemm_mma<<<gemm_grid, 256>>>(p_h, p_w1hi, p_w1lo, al1, ar1, p_featb, p_el, p_er, HID);
    agg_kernel<<<agg_grid, 256>>>(p_featb, p_el, p_er, b1, p_h);

    // output layer: classifier GEMM with fused el2/er2, then aggregation
    gemm_mma2<<<(NN + 127) / 128, 256>>>(p_h, p_w2hi, p_w2lo, al2, ar2,
                                         p_feat2, p_el2, p_er2);
    agg2_kernel<<<agg_grid, 256>>>(p_feat2, p_el2, p_er2, b2, out);
}

// round 10
// speedup vs baseline: 1.1901x; 1.1901x over previous
#include <cuda_runtime.h>
#include <cuda_bf16.h>
#include <math.h>
#include <stdint.h>

#define NN 50000
#define NE 800000
#define NHEADS 8
#define HID 256
#define NCLS 40
#define NEG 0.2f

// ---------------- scratch (static device allocations; no cudaMalloc) ----------------
__device__ __nv_bfloat16 g_featb[(size_t)NN * HID];
__device__ float g_hbuf[(size_t)NN * HID];
__device__ float g_feat2[(size_t)NN * NCLS];
__device__ float g_el[NN * NHEADS];
__device__ float g_er[NN * NHEADS];
__device__ float g_el2[NN];
__device__ float g_er2[NN];
__device__ int   g_deg[NN];
__device__ int   g_cur[NN];
__device__ int   g_off[NN + 1];
__device__ int   g_csr_src[NE];
__device__ __nv_bfloat16 g_w0hi[512 * HID];
__device__ __nv_bfloat16 g_w0lo[512 * HID];
__device__ __nv_bfloat16 g_w1hi[HID * HID];
__device__ __nv_bfloat16 g_w1lo[HID * HID];
__device__ __nv_bfloat16 g_w2hi[64 * HID];   // rows 40..63 stay zero
__device__ __nv_bfloat16 g_w2lo[64 * HID];

// ---------------- CSR build ----------------
__global__ void zero_counts_kernel() {
    int i = blockIdx.x * blockDim.x + threadIdx.x;
    if (i < NN) { g_deg[i] = 0; g_cur[i] = 0; }
}
__global__ void hist_kernel(const int* __restrict__ dst) {
    int e = blockIdx.x * blockDim.x + threadIdx.x;
    if (e < NE) atomicAdd(&g_deg[dst[e]], 1);
}
__global__ void scan_kernel() {
    __shared__ int sums[1024];
    int t = threadIdx.x;
    const int chunk = (NN + 1023) / 1024;
    int start = t * chunk;
    int end = min(start + chunk, NN);
    int s = 0;
    for (int i = start; i < end; i++) s += g_deg[i];
    sums[t] = s;
    __syncthreads();
    for (int off = 1; off < 1024; off <<= 1) {
        int v = (t >= off) ? sums[t - off] : 0;
        __syncthreads();
        sums[t] += v;
        __syncthreads();
    }
    int run = (t == 0) ? 0 : sums[t - 1];
    for (int i = start; i < end; i++) { g_off[i] = run; run += g_deg[i]; }
    if (t == 1023) g_off[NN] = sums[1023];
}
__global__ void scatter_kernel(const int* __restrict__ src, const int* __restrict__ dst) {
    int e = blockIdx.x * blockDim.x + threadIdx.x;
    if (e < NE) {
        int d = dst[e];
        int pos = g_off[d] + atomicAdd(&g_cur[d], 1);
        g_csr_src[pos] = src[e];
    }
}

// ---------------- weight prep: W[K,Ncols] fp32 -> Wt[Ncols,K] bf16 hi/lo ----------------
__global__ void prep_wt(const float* __restrict__ W, __nv_bfloat16* __restrict__ hi,
                        __nv_bfloat16* __restrict__ lo, int K, int Ncols) {
    int idx = blockIdx.x * blockDim.x + threadIdx.x;
    if (idx >= K * Ncols) return;
    int k = idx / Ncols;
    int n = idx - k * Ncols;
    float x = W[idx];
    __nv_bfloat16 h = __float2bfloat16(x);
    float r = x - __bfloat162float(h);
    hi[(size_t)n * K + k] = h;
    lo[(size_t)n * K + k] = __float2bfloat16(r);
}

// ---------------- warp-mma bf16-split GEMM (3-term), pipelined, fused el/er ----------------
#define SPITCH 20

#define MMA_BF16(c, a, b)                                                           \
    asm volatile(                                                                   \
        "mma.sync.aligned.m16n8k16.row.col.f32.bf16.bf16.f32 "                      \
        "{%0,%1,%2,%3},{%4,%5,%6,%7},{%8,%9},{%0,%1,%2,%3};"                        \
        : "+f"((c)[0]), "+f"((c)[1]), "+f"((c)[2]), "+f"((c)[3])                    \
        : "r"((a)[0]), "r"((a)[1]), "r"((a)[2]), "r"((a)[3]),                       \
          "r"((b)[0]), "r"((b)[1]))

__global__ __launch_bounds__(256, 1) void gemm_mma(
    const float* __restrict__ A, const __nv_bfloat16* __restrict__ Bhi,
    const __nv_bfloat16* __restrict__ Blo, const float* __restrict__ alv,
    const float* __restrict__ arv, __nv_bfloat16* __restrict__ featb,
    float* __restrict__ el, float* __restrict__ er, int K)
{
    __shared__ uint32_t sAh[128 * SPITCH];
    __shared__ uint32_t sAl[128 * SPITCH];
    __shared__ uint32_t sBh[128 * SPITCH];
    __shared__ uint32_t sBl[128 * SPITCH];

    int tid = threadIdx.x, lane = tid & 31, wid = tid >> 5;
    int wm = wid & 1, wn = wid >> 1;
    int row0 = blockIdx.x * 128;
    int col0 = blockIdx.y * 128;
    const uint2* Bh64 = (const uint2*)Bhi;
    const uint2* Bl64 = (const uint2*)Blo;
    int Kq = K >> 2;

    int lr = tid >> 3;
    int lq = tid & 7;

    float acc[4][4][4];
#pragma unroll
    for (int i = 0; i < 4; i++)
#pragma unroll
        for (int j = 0; j < 4; j++)
#pragma unroll
            for (int q = 0; q < 4; q++) acc[i][j][q] = 0.f;

    float4 pa[4];
    uint2 pbh[4], pbl[4];
    int nch = K >> 5;

#pragma unroll
    for (int i = 0; i < 4; i++) {
        int r = lr + i * 32;
        pa[i] = (row0 + r < NN)
            ? *(const float4*)(A + (size_t)(row0 + r) * K + lq * 4)
            : make_float4(0.f, 0.f, 0.f, 0.f);
        pbh[i] = Bh64[(size_t)(col0 + r) * Kq + lq];
        pbl[i] = Bl64[(size_t)(col0 + r) * Kq + lq];
    }

    for (int c = 0; c < nch; c++) {
#pragma unroll
        for (int i = 0; i < 4; i++) {
            int r = lr + i * 32;
            float4 v = pa[i];
            __nv_bfloat16 h0 = __float2bfloat16(v.x);
            __nv_bfloat16 h1 = __float2bfloat16(v.y);
            __nv_bfloat16 h2 = __float2bfloat16(v.z);
            __nv_bfloat16 h3 = __float2bfloat16(v.w);
            __nv_bfloat16 l0 = __float2bfloat16(v.x - __bfloat162float(h0));
            __nv_bfloat16 l1 = __float2bfloat16(v.y - __bfloat162float(h1));
            __nv_bfloat16 l2 = __float2bfloat16(v.z - __bfloat162float(h2));
            __nv_bfloat16 l3 = __float2bfloat16(v.w - __bfloat162float(h3));
            int sb = r * SPITCH + lq * 2;
            sAh[sb]     = (uint32_t)__bfloat16_as_ushort(h0) | ((uint32_t)__bfloat16_as_ushort(h1) << 16);
            sAh[sb + 1] = (uint32_t)__bfloat16_as_ushort(h2) | ((uint32_t)__bfloat16_as_ushort(h3) << 16);
            sAl[sb]     = (uint32_t)__bfloat16_as_ushort(l0) | ((uint32_t)__bfloat16_as_ushort(l1) << 16);
            sAl[sb + 1] = (uint32_t)__bfloat16_as_ushort(l2) | ((uint32_t)__bfloat16_as_ushort(l3) << 16);
            sBh[sb]     = pbh[i].x;
            sBh[sb + 1] = pbh[i].y;
            sBl[sb]     = pbl[i].x;
            sBl[sb + 1] = pbl[i].y;
        }
        __syncthreads();

        if (c + 1 < nch) {
            int ko = (c + 1) << 5;
#pragma unroll
            for (int i = 0; i < 4; i++) {
                int r = lr + i * 32;
                pa[i] = (row0 + r < NN)
                    ? *(const float4*)(A + (size_t)(row0 + r) * K + ko + lq * 4)
                    : make_float4(0.f, 0.f, 0.f, 0.f);
                pbh[i] = Bh64[(size_t)(col0 + r) * Kq + ((c + 1) << 3) + lq];
                pbl[i] = Bl64[(size_t)(col0 + r) * Kq + ((c + 1) << 3) + lq];
            }
        }

#pragma unroll
        for (int ks = 0; ks < 2; ks++) {
            int kb = (ks << 3) + (lane & 3);
            uint32_t ah[4][4], al_[4][4], bh[4][2], bl[4][2];
#pragma unroll
            for (int am = 0; am < 4; am++) {
                int rb = (wm * 64 + am * 16 + (lane >> 2)) * SPITCH;
                ah[am][0] = sAh[rb + kb];
                ah[am][1] = sAh[rb + 8 * SPITCH + kb];
                ah[am][2] = sAh[rb + kb + 4];
                ah[am][3] = sAh[rb + 8 * SPITCH + kb + 4];
                al_[am][0] = sAl[rb + kb];
                al_[am][1] = sAl[rb + 8 * SPITCH + kb];
                al_[am][2] = sAl[rb + kb + 4];
                al_[am][3] = sAl[rb + 8 * SPITCH + kb + 4];
            }
#pragma unroll
            for (int an = 0; an < 4; an++) {
                int nb = (wn * 32 + an * 8 + (lane >> 2)) * SPITCH;
                bh[an][0] = sBh[nb + kb];
                bh[an][1] = sBh[nb + kb + 4];
                bl[an][0] = sBl[nb + kb];
                bl[an][1] = sBl[nb + kb + 4];
            }
#pragma unroll
            for (int am = 0; am < 4; am++)
#pragma unroll
                for (int an = 0; an < 4; an++) {
                    MMA_BF16(acc[am][an], ah[am], bh[an]);
                    MMA_BF16(acc[am][an], ah[am], bl[an]);
                    MMA_BF16(acc[am][an], al_[am], bh[an]);
                }
        }
        __syncthreads();
    }

    int h = blockIdx.y * 4 + wn;
    float alr[8], arr[8];
#pragma unroll
    for (int an = 0; an < 4; an++) {
        int cc = an * 8 + 2 * (lane & 3);
        alr[an * 2]     = __ldg(alv + h * 32 + cc);
        alr[an * 2 + 1] = __ldg(alv + h * 32 + cc + 1);
        arr[an * 2]     = __ldg(arv + h * 32 + cc);
        arr[an * 2 + 1] = __ldg(arv + h * 32 + cc + 1);
    }
#pragma unroll
    for (int am = 0; am < 4; am++) {
        int r0 = row0 + wm * 64 + am * 16 + (lane >> 2);
        int r1 = r0 + 8;
        float sl0 = 0.f, sr0 = 0.f, sl1 = 0.f, sr1 = 0.f;
#pragma unroll
        for (int an = 0; an < 4; an++) {
            float c0 = acc[am][an][0], c1 = acc[am][an][1];
            float c2 = acc[am][an][2], c3 = acc[am][an][3];
            sl0 = fmaf(c0, alr[an * 2], fmaf(c1, alr[an * 2 + 1], sl0));
            sr0 = fmaf(c0, arr[an * 2], fmaf(c1, arr[an * 2 + 1], sr0));
            sl1 = fmaf(c2, alr[an * 2], fmaf(c3, alr[an * 2 + 1], sl1));
            sr1 = fmaf(c2, arr[an * 2], fmaf(c3, arr[an * 2 + 1], sr1));
            int ccol = col0 + wn * 32 + an * 8 + 2 * (lane & 3);
            __nv_bfloat162 p0 = __float22bfloat162_rn(make_float2(c0, c1));
            __nv_bfloat162 p1 = __float22bfloat162_rn(make_float2(c2, c3));
            if (r0 < NN) *(__nv_bfloat162*)(featb + (size_t)r0 * HID + ccol) = p0;
            if (r1 < NN) *(__nv_bfloat162*)(featb + (size_t)r1 * HID + ccol) = p1;
        }
        sl0 += __shfl_xor_sync(0xFFFFFFFFu, sl0, 1);
        sl0 += __shfl_xor_sync(0xFFFFFFFFu, sl0, 2);
        sr0 += __shfl_xor_sync(0xFFFFFFFFu, sr0, 1);
        sr0 += __shfl_xor_sync(0xFFFFFFFFu, sr0, 2);
        sl1 += __shfl_xor_sync(0xFFFFFFFFu, sl1, 1);
        sl1 += __shfl_xor_sync(0xFFFFFFFFu, sl1, 2);
        sr1 += __shfl_xor_sync(0xFFFFFFFFu, sr1, 1);
        sr1 += __shfl_xor_sync(0xFFFFFFFFu, sr1, 2);
        if ((lane & 3) == 0) {
            if (r0 < NN) { el[r0 * NHEADS + h] = sl0; er[r0 * NHEADS + h] = sr0; }
            if (r1 < NN) { el[r1 * NHEADS + h] = sl1; er[r1 * NHEADS + h] = sr1; }
        }
    }
}

// ---------------- classifier GEMM + fused el2/er2: feat2[M,40] = A[M,256] @ W2 ----------------
__global__ __launch_bounds__(256, 1) void gemm_mma2(
    const float* __restrict__ A, const __nv_bfloat16* __restrict__ Bhi,
    const __nv_bfloat16* __restrict__ Blo, const float* __restrict__ al2,
    const float* __restrict__ ar2, float* __restrict__ feat2,
    float* __restrict__ el2, float* __restrict__ er2)
{
    __shared__ uint32_t sAh[128 * SPITCH];
    __shared__ uint32_t sAl[128 * SPITCH];
    __shared__ uint32_t sBh[64 * SPITCH];
    __shared__ uint32_t sBl[64 * SPITCH];
    __shared__ float sEl[128], sEr[128];

    const int K = HID;
    int tid = threadIdx.x, lane = tid & 31, wid = tid >> 5;
    int wm = wid & 1, wn = wid >> 1;
    int row0 = blockIdx.x * 128;
    const uint2* Bh64 = (const uint2*)Bhi;
    const uint2* Bl64 = (const uint2*)Blo;
    const int Kq = K >> 2;

    int lr = tid >> 3;
    int lq = tid & 7;

    float acc[4][2][4];
#pragma unroll
    for (int i = 0; i < 4; i++)
#pragma unroll
        for (int j = 0; j < 2; j++)
#pragma unroll
            for (int q = 0; q < 4; q++) acc[i][j][q] = 0.f;

    float4 pa[4];
    uint2 pbh[2], pbl[2];
    const int nch = K >> 5;

#pragma unroll
    for (int i = 0; i < 4; i++) {
        int r = lr + i * 32;
        pa[i] = (row0 + r < NN)
            ? *(const float4*)(A + (size_t)(row0 + r) * K + lq * 4)
            : make_float4(0.f, 0.f, 0.f, 0.f);
    }
#pragma unroll
    for (int i = 0; i < 2; i++) {
        int r = lr + i * 32;
        pbh[i] = Bh64[(size_t)r * Kq + lq];
        pbl[i] = Bl64[(size_t)r * Kq + lq];
    }

    for (int c = 0; c < nch; c++) {
#pragma unroll
        for (int i = 0; i < 4; i++) {
            int r = lr + i * 32;
            float4 v = pa[i];
            __nv_bfloat16 h0 = __float2bfloat16(v.x);
            __nv_bfloat16 h1 = __float2bfloat16(v.y);
            __nv_bfloat16 h2 = __float2bfloat16(v.z);
            __nv_bfloat16 h3 = __float2bfloat16(v.w);
            __nv_bfloat16 l0 = __float2bfloat16(v.x - __bfloat162float(h0));
            __nv_bfloat16 l1 = __float2bfloat16(v.y - __bfloat162float(h1));
            __nv_bfloat16 l2 = __float2bfloat16(v.z - __bfloat162float(h2));
            __nv_bfloat16 l3 = __float2bfloat16(v.w - __bfloat162float(h3));
            int sb = r * SPITCH + lq * 2;
            sAh[sb]     = (uint32_t)__bfloat16_as_ushort(h0) | ((uint32_t)__bfloat16_as_ushort(h1) << 16);
            sAh[sb + 1] = (uint32_t)__bfloat16_as_ushort(h2) | ((uint32_t)__bfloat16_as_ushort(h3) << 16);
            sAl[sb]     = (uint32_t)__bfloat16_as_ushort(l0) | ((uint32_t)__bfloat16_as_ushort(l1) << 16);
            sAl[sb + 1] = (uint32_t)__bfloat16_as_ushort(l2) | ((uint32_t)__bfloat16_as_ushort(l3) << 16);
        }
#pragma unroll
        for (int i = 0; i < 2; i++) {
            int r = lr + i * 32;
            int sb = r * SPITCH + lq * 2;
            sBh[sb]     = pbh[i].x;
            sBh[sb + 1] = pbh[i].y;
            sBl[sb]     = pbl[i].x;
            sBl[sb + 1] = pbl[i].y;
        }
        __syncthreads();

        if (c + 1 < nch) {
            int ko = (c + 1) << 5;
#pragma unroll
            for (int i = 0; i < 4; i++) {
                int r = lr + i * 32;
                pa[i] = (row0 + r < NN)
                    ? *(const float4*)(A + (size_t)(row0 + r) * K + ko + lq * 4)
                    : make_float4(0.f, 0.f, 0.f, 0.f);
            }
#pragma unroll
            for (int i = 0; i < 2; i++) {
                int r = lr + i * 32;
                pbh[i] = Bh64[(size_t)r * Kq + ((c + 1) << 3) + lq];
                pbl[i] = Bl64[(size_t)r * Kq + ((c + 1) << 3) + lq];
            }
        }

#pragma unroll
        for (int ks = 0; ks < 2; ks++) {
            int kb = (ks << 3) + (lane & 3);
            uint32_t ah[4][4], al_[4][4], bh[2][2], bl[2][2];
#pragma unroll
            for (int am = 0; am < 4; am++) {
                int rb = (wm * 64 + am * 16 + (lane >> 2)) * SPITCH;
                ah[am][0] = sAh[rb + kb];
                ah[am][1] = sAh[rb + 8 * SPITCH + kb];
                ah[am][2] = sAh[rb + kb + 4];
                ah[am][3] = sAh[rb + 8 * SPITCH + kb + 4];
                al_[am][0] = sAl[rb + kb];
                al_[am][1] = sAl[rb + 8 * SPITCH + kb];
                al_[am][2] = sAl[rb + kb + 4];
                al_[am][3] = sAl[rb + 8 * SPITCH + kb + 4];
            }
#pragma unroll
            for (int an = 0; an < 2; an++) {
                int nb = (wn * 16 + an * 8 + (lane >> 2)) * SPITCH;
                bh[an][0] = sBh[nb + kb];
                bh[an][1] = sBh[nb + kb + 4];
                bl[an][0] = sBl[nb + kb];
                bl[an][1] = sBl[nb + kb + 4];
            }
#pragma unroll
            for (int am = 0; am < 4; am++)
#pragma unroll
                for (int an = 0; an < 2; an++) {
                    MMA_BF16(acc[am][an], ah[am], bh[an]);
                    MMA_BF16(acc[am][an], ah[am], bl[an]);
                    MMA_BF16(acc[am][an], al_[am], bh[an]);
                }
        }
        __syncthreads();
    }

    // fused el2/er2
    if (tid < 128) { sEl[tid] = 0.f; sEr[tid] = 0.f; }
    __syncthreads();

    float av[4], rv[4];
#pragma unroll
    for (int an = 0; an < 2; an++) {
        int cc = wn * 16 + an * 8 + 2 * (lane & 3);
        av[an * 2]     = (cc < NCLS)     ? __ldg(al2 + cc)     : 0.f;
        av[an * 2 + 1] = (cc + 1 < NCLS) ? __ldg(al2 + cc + 1) : 0.f;
        rv[an * 2]     = (cc < NCLS)     ? __ldg(ar2 + cc)     : 0.f;
        rv[an * 2 + 1] = (cc + 1 < NCLS) ? __ldg(ar2 + cc + 1) : 0.f;
    }

#pragma unroll
    for (int am = 0; am < 4; am++) {
        int rl0 = wm * 64 + am * 16 + (lane >> 2);
        int rl1 = rl0 + 8;
        int r0 = row0 + rl0, r1 = row0 + rl1;
        float sl0 = 0.f, sr0 = 0.f, sl1 = 0.f, sr1 = 0.f;
#pragma unroll
        for (int an = 0; an < 2; an++) {
            float c0 = acc[am][an][0], c1 = acc[am][an][1];
            float c2 = acc[am][an][2], c3 = acc[am][an][3];
            sl0 = fmaf(c0, av[an * 2], fmaf(c1, av[an * 2 + 1], sl0));
            sr0 = fmaf(c0, rv[an * 2], fmaf(c1, rv[an * 2 + 1], sr0));
            sl1 = fmaf(c2, av[an * 2], fmaf(c3, av[an * 2 + 1], sl1));
            sr1 = fmaf(c2, rv[an * 2], fmaf(c3, rv[an * 2 + 1], sr1));
            int ccol = wn * 16 + an * 8 + 2 * (lane & 3);
            if (ccol < NCLS) {
                if (r0 < NN)
                    *(float2*)(feat2 + (size_t)r0 * NCLS + ccol) = make_float2(c0, c1);
                if (r1 < NN)
                    *(float2*)(feat2 + (size_t)r1 * NCLS + ccol) = make_float2(c2, c3);
            }
        }
        sl0 += __shfl_xor_sync(0xFFFFFFFFu, sl0, 1);
        sl0 += __shfl_xor_sync(0xFFFFFFFFu, sl0, 2);
        sr0 += __shfl_xor_sync(0xFFFFFFFFu, sr0, 1);
        sr0 += __shfl_xor_sync(0xFFFFFFFFu, sr0, 2);
        sl1 += __shfl_xor_sync(0xFFFFFFFFu, sl1, 1);
        sl1 += __shfl_xor_sync(0xFFFFFFFFu, sl1, 2);
        sr1 += __shfl_xor_sync(0xFFFFFFFFu, sr1, 1);
        sr1 += __shfl_xor_sync(0xFFFFFFFFu, sr1, 2);
        if ((lane & 3) == 0) {
            atomicAdd(&sEl[rl0], sl0);
            atomicAdd(&sEr[rl0], sr0);
            atomicAdd(&sEl[rl1], sl1);
            atomicAdd(&sEr[rl1], sr1);
        }
    }
    __syncthreads();
    if (tid < 128) {
        int r = row0 + tid;
        if (r < NN) { el2[r] = sEl[tid]; er2[r] = sEr[tid]; }
    }
}

// ---------------- per-dst online-softmax aggregation (bf16 msgs, H=8, D=32) ----------------
__global__ __launch_bounds__(256) void agg_kernel(const __nv_bfloat16* __restrict__ featb,
                                                  const float* __restrict__ el,
                                                  const float* __restrict__ er,
                                                  const float* __restrict__ bias,
                                                  float* __restrict__ out) {
    int gw = (blockIdx.x * blockDim.x + threadIdx.x) >> 5;
    int lane = threadIdx.x & 31;
    if (gw >= NN) return;
    int h = lane >> 2;
    float erh = er[gw * NHEADS + h];
    int e0 = g_off[gw], e1 = g_off[gw + 1];
    float m = -1e30f, den = 0.f;
    float ac[8];
#pragma unroll
    for (int j = 0; j < 8; j++) ac[j] = 0.f;

    for (int i = e0; i < e1; i++) {
        int s = g_csr_src[i];
        float sc = el[s * NHEADS + h] + erh;
        sc = (sc > 0.f) ? sc : NEG * sc;
        float mn = fmaxf(m, sc);
        float scale = __expf(m - mn);
        float p = __expf(sc - mn);
        m = mn;
        uint4 raw = *(const uint4*)(featb + (size_t)s * HID + lane * 8);
        float2 f0 = __bfloat1622float2(*(__nv_bfloat162*)&raw.x);
        float2 f1 = __bfloat1622float2(*(__nv_bfloat162*)&raw.y);
        float2 f2 = __bfloat1622float2(*(__nv_bfloat162*)&raw.z);
        float2 f3 = __bfloat1622float2(*(__nv_bfloat162*)&raw.w);
        den = den * scale + p;
        ac[0] = fmaf(p, f0.x, ac[0] * scale);
        ac[1] = fmaf(p, f0.y, ac[1] * scale);
        ac[2] = fmaf(p, f1.x, ac[2] * scale);
        ac[3] = fmaf(p, f1.y, ac[3] * scale);
        ac[4] = fmaf(p, f2.x, ac[4] * scale);
        ac[5] = fmaf(p, f2.y, ac[5] * scale);
        ac[6] = fmaf(p, f3.x, ac[6] * scale);
        ac[7] = fmaf(p, f3.y, ac[7] * scale);
    }
    float rinv = 1.f / fmaxf(den, 1e-9f);
    float4 b0 = *(const float4*)(bias + lane * 8);
    float4 b1 = *(const float4*)(bias + lane * 8 + 4);
    float4 o0, o1;
    o0.x = fmaxf(fmaf(ac[0], rinv, b0.x), 0.f);
    o0.y = fmaxf(fmaf(ac[1], rinv, b0.y), 0.f);
    o0.z = fmaxf(fmaf(ac[2], rinv, b0.z), 0.f);
    o0.w = fmaxf(fmaf(ac[3], rinv, b0.w), 0.f);
    o1.x = fmaxf(fmaf(ac[4], rinv, b1.x), 0.f);
    o1.y = fmaxf(fmaf(ac[5], rinv, b1.y), 0.f);
    o1.z = fmaxf(fmaf(ac[6], rinv, b1.z), 0.f);
    o1.w = fmaxf(fmaf(ac[7], rinv, b1.w), 0.f);
    float4* op = (float4*)(out + (size_t)gw * HID + lane * 8);
    op[0] = o0;
    op[1] = o1;
}

// ---------------- classifier aggregation (H=1, D=40), no relu ----------------
__global__ __launch_bounds__(256) void agg2_kernel(const float* __restrict__ feat,
                                                   const float* __restrict__ el,
                                                   const float* __restrict__ er,
                                                   const float* __restrict__ bias,
                                                   float* __restrict__ out) {
    int gw = (blockIdx.x * blockDim.x + threadIdx.x) >> 5;
    int lane = threadIdx.x & 31;
    if (gw >= NN) return;
    float ern = er[gw];
    int e0 = g_off[gw], e1 = g_off[gw + 1];
    float m = -1e30f, den = 0.f, a0 = 0.f, a1 = 0.f;
    for (int i = e0; i < e1; i++) {
        int s = g_csr_src[i];
        float sc = el[s] + ern;
        sc = (sc > 0.f) ? sc : NEG * sc;
        float mn = fmaxf(m, sc);
        float scale = __expf(m - mn);
        float p = __expf(sc - mn);
        m = mn;
        float f0 = feat[(size_t)s * NCLS + lane];
        float f1 = (lane < 8) ? feat[(size_t)s * NCLS + 32 + lane] : 0.f;
        den = den * scale + p;
        a0 = fmaf(p, f0, a0 * scale);
        a1 = fmaf(p, f1, a1 * scale);
    }
    float rinv = 1.f / fmaxf(den, 1e-9f);
    out[(size_t)gw * NCLS + lane] = fmaf(a0, rinv, bias[lane]);
    if (lane < 8)
        out[(size_t)gw * NCLS + 32 + lane] = fmaf(a1, rinv, bias[32 + lane]);
}

// ---------------- launch ----------------
extern "C" void kernel_launch(void* const* d_in, const int* in_sizes, int n_in,
                              void* d_out, int out_size) {
    const float* in_feat = (const float*)d_in[0];
    const int*   src     = (const int*)d_in[1];
    const int*   dst     = (const int*)d_in[2];
    const float* W0  = (const float*)d_in[3];
    const float* al0 = (const float*)d_in[4];
    const float* ar0 = (const float*)d_in[5];
    const float* b0  = (const float*)d_in[6];
    const float* W1  = (const float*)d_in[7];
    const float* al1 = (const float*)d_in[8];
    const float* ar1 = (const float*)d_in[9];
    const float* b1  = (const float*)d_in[10];
    const float* W2  = (const float*)d_in[11];
    const float* al2 = (const float*)d_in[12];
    const float* ar2 = (const float*)d_in[13];
    const float* b2  = (const float*)d_in[14];
    float* out = (float*)d_out;

    float *p_h, *p_feat2, *p_el, *p_er, *p_el2, *p_er2;
    __nv_bfloat16 *p_featb, *p_w0hi, *p_w0lo, *p_w1hi, *p_w1lo, *p_w2hi, *p_w2lo;
    cudaGetSymbolAddress((void**)&p_featb, g_featb);
    cudaGetSymbolAddress((void**)&p_h, g_hbuf);
    cudaGetSymbolAddress((void**)&p_feat2, g_feat2);
    cudaGetSymbolAddress((void**)&p_el, g_el);
    cudaGetSymbolAddress((void**)&p_er, g_er);
    cudaGetSymbolAddress((void**)&p_el2, g_el2);
    cudaGetSymbolAddress((void**)&p_er2, g_er2);
    cudaGetSymbolAddress((void**)&p_w0hi, g_w0hi);
    cudaGetSymbolAddress((void**)&p_w0lo, g_w0lo);
    cudaGetSymbolAddress((void**)&p_w1hi, g_w1hi);
    cudaGetSymbolAddress((void**)&p_w1lo, g_w1lo);
    cudaGetSymbolAddress((void**)&p_w2hi, g_w2hi);
    cudaGetSymbolAddress((void**)&p_w2lo, g_w2lo);

    // lazily-created side stream + events (created once, outside any capture)
    static cudaStream_t s_side = nullptr;
    static cudaEvent_t s_fork = nullptr, s_join = nullptr;
    if (s_side == nullptr) {
        cudaStreamCreateWithFlags(&s_side, cudaStreamNonBlocking);
        cudaEventCreateWithFlags(&s_fork, cudaEventDisableTiming);
        cudaEventCreateWithFlags(&s_join, cudaEventDisableTiming);
    }

    // ---- fork: CSR build + W1/W2 prep on side stream ----
    cudaEventRecord(s_fork, 0);
    cudaStreamWaitEvent(s_side, s_fork, 0);
    zero_counts_kernel<<<(NN + 255) / 256, 256, 0, s_side>>>();
    hist_kernel<<<(NE + 255) / 256, 256, 0, s_side>>>(dst);
    scan_kernel<<<1, 1024, 0, s_side>>>();
    scatter_kernel<<<(NE + 255) / 256, 256, 0, s_side>>>(src, dst);
    prep_wt<<<(HID * HID + 255) / 256, 256, 0, s_side>>>(W1, p_w1hi, p_w1lo, HID, HID);
    prep_wt<<<(HID * NCLS + 255) / 256, 256, 0, s_side>>>(W2, p_w2hi, p_w2lo, HID, NCLS);
    cudaEventRecord(s_join, s_side);

    // ---- main stream: W0 prep + GEMM layer 0 ----
    prep_wt<<<(512 * HID + 255) / 256, 256>>>(W0, p_w0hi, p_w0lo, 512, HID);

    dim3 gemm_grid((NN + 127) / 128, 2);
    int agg_grid = (NN * 32 + 255) / 256;

    gemm_mma<<<gemm_grid, 256>>>(in_feat, p_w0hi, p_w0lo, al0, ar0,
                                 p_featb, p_el, p_er, 512);

    // join side stream before aggregation
    cudaStreamWaitEvent(0, s_join, 0);
    agg_kernel<<<agg_grid, 256>>>(p_featb, p_el, p_er, b0, p_h);

    // layer 1
    gemm_mma<<<gemm_grid, 256>>>(p_h, p_w1hi, p_w1lo, al1, ar1, p_featb, p_el, p_er, HID);
    agg_kernel<<<agg_grid, 256>>>(p_featb, p_el, p_er, b1, p_h);

    // output layer: classifier GEMM with fused el2/er2, then aggregation
    gemm_mma2<<<(NN + 127) / 128, 256>>>(p_h, p_w2hi, p_w2lo, al2, ar2,
                                         p_feat2, p_el2, p_er2);
    agg2_kernel<<<agg_grid, 256>>>(p_feat2, p_el2, p_er2, b2, out);
}